// round 12
// baseline (speedup 1.0000x reference)
#include <cuda_runtime.h>
#include <math.h>

#define NPTS   2048
#define NT     128
#define NW     (NT/32)      // 4 warps
#define MAXPTS 100
#define F_INF  (__int_as_float(0x7f800000))

typedef unsigned long long u64;
typedef unsigned int       u32;

static __device__ __forceinline__ u64 umin64(u64 a, u64 b) { return a < b ? a : b; }
static __device__ __forceinline__ u64 umax64(u64 a, u64 b) { return a > b ? a : b; }

template<int E> struct Regs { float x2[E], y2[E], z2[E], sq[E], mk[E]; };

// value-only min tree: pure FMNMX, 4 cyc/level (fold non-pow2 tail onto first 8)
template<int E>
static __device__ __forceinline__ float vmin_tree(const float (&v)[E])
{
    float bv[E];
    #pragma unroll
    for (int e = 0; e < E; e++) bv[e] = v[e];
    constexpr int T = (E > 8) ? 8 : E;
    #pragma unroll
    for (int e = T; e < E; e++) bv[e - T] = fminf(bv[e - T], bv[e]);
    #pragma unroll
    for (int st = T / 2; st >= 1; st >>= 1)
        #pragma unroll
        for (int e = 0; e < st; e++) bv[e] = fminf(bv[e], bv[e + st]);
    return bv[0];
}

template<int E>
static __device__ __forceinline__ float vmax_tree(const float (&v)[E])
{
    float bv[E];
    #pragma unroll
    for (int e = 0; e < E; e++) bv[e] = v[e];
    constexpr int T = (E > 8) ? 8 : E;
    #pragma unroll
    for (int e = T; e < E; e++) bv[e - T] = fmaxf(bv[e - T], bv[e]);
    #pragma unroll
    for (int st = T / 2; st >= 1; st >>= 1)
        #pragma unroll
        for (int e = 0; e < st; e++) bv[e] = fmaxf(bv[e], bv[e + st]);
    return bv[0];
}

// index recovery: independent ISETP/SEL per element + OR-tree + FFS.
// Depends only on (v, target) -> overlaps the warp-REDUX latency.
template<int E>
static __device__ __forceinline__ int idx_of(const float (&v)[E], float target)
{
    u32 m = 0;
    #pragma unroll
    for (int e = 0; e < E; e++) m |= (v[e] == target) ? (1u << e) : 0u;
    return __ffs(m) - 1;
}

// ---------- multi-warp Prim phase (tbl = raw (x,y,z,|x|^2); regs hold -2x) ----------
template<int E>
static __device__ __forceinline__ void prim_run(
    const float4* __restrict__ tbl, float* __restrict__ sdeath,
    u64 (&wred)[2][NW], Regs<E>& R,
    int gbase, int tid, int wid,
    int& j, int& p, int step0, int nsteps)
{
    const float inf = F_INF;
    #pragma unroll 1
    for (int s = 0; s < nsteps; s++) {
        float4 q = tbl[j];                        // LDS.128 broadcast
        #pragma unroll
        for (int e = 0; e < E; e++) {
            int gi = gbase + e;
            bool rem = (gi == j);
            float rs = rem ? inf : R.sq[e];       // permanent poison of removed vertex
            R.sq[e] = rs;
            float acc = fmaf(q.x, R.x2[e], rs + q.w);
            acc = fmaf(q.y, R.y2[e], acc);
            acc = fmaf(q.z, R.z2[e], acc);
            float mi = rem ? inf : R.mk[e];
            R.mk[e] = fminf(mi, fabsf(acc));      // >=0 -> u32 bit-order exact
        }
        float tm = vmin_tree<E>(R.mk);            // short FMNMX chain
        u32 vb = __float_as_uint(tm);
        u32 r1 = __reduce_min_sync(0xffffffffu, vb);
        int te = idx_of<E>(R.mk, tm);             // overlaps REDUX latency
        if (vb == r1)
            wred[p][wid] = ((u64)r1 << 32) | (u64)(u32)(gbase + te);

        __syncthreads();

        u64 a0 = umin64(wred[p][0], wred[p][1]);
        u64 a1 = umin64(wred[p][2], wred[p][3]);
        a0 = umin64(a0, a1);
        if (tid == 0) sdeath[step0 + s] = __uint_as_float((u32)(a0 >> 32));
        j = (int)(u32)a0;
        p ^= 1;
    }
}

// ---------- single-warp Prim phase (warp 0, no block barriers) ----------
template<int E>
static __device__ __forceinline__ void prim_warp(
    const float4* __restrict__ tbl, float* __restrict__ sdeath,
    Regs<E>& R, int gbase, int lane, int& j, int step0, int nsteps)
{
    const float inf = F_INF;
    #pragma unroll 1
    for (int s = 0; s < nsteps; s++) {
        float4 q = tbl[j];
        #pragma unroll
        for (int e = 0; e < E; e++) {
            int gi = gbase + e;
            bool rem = (gi == j);
            float rs = rem ? inf : R.sq[e];
            R.sq[e] = rs;
            float acc = fmaf(q.x, R.x2[e], rs + q.w);
            acc = fmaf(q.y, R.y2[e], acc);
            acc = fmaf(q.z, R.z2[e], acc);
            float mi = rem ? inf : R.mk[e];
            R.mk[e] = fminf(mi, fabsf(acc));
        }
        float tm = vmin_tree<E>(R.mk);
        u32 vb = __float_as_uint(tm);
        u32 r1 = __reduce_min_sync(0xffffffffu, vb);
        int te = idx_of<E>(R.mk, tm);             // overlaps REDUX
        u32 msk = __ballot_sync(0xffffffffu, vb == r1);
        int src = __ffs(msk) - 1;
        j = __shfl_sync(0xffffffffu, gbase + te, src);
        if (lane == 0) sdeath[step0 + s] = __uint_as_float(r1);
    }
}

// ---------- block-wide compaction: alive -> tbl[0..newcap-2], winner at newcap-1 ----------
template<int E>
static __device__ __forceinline__ void compact_block(
    float4* tbl, float* smk, int* scnt,
    Regs<E>& R, int gbase, int tid, int j, int newcap)
{
    const float inf = F_INF;
    #pragma unroll
    for (int e = 0; e < E; e++)
        if (gbase + e == j) { R.sq[e] = inf; R.mk[e] = inf; }   // pending poison
    float4 win = tbl[j];                    // read winner BEFORE overwrite
    __syncthreads();
    if (tid == 0) { tbl[newcap - 1] = win; smk[newcap - 1] = inf; }
    int na = 0;
    #pragma unroll
    for (int e = 0; e < E; e++) na += (R.mk[e] != inf);
    int base = atomicAdd(scnt, na);
    #pragma unroll
    for (int e = 0; e < E; e++) {
        if (R.mk[e] != inf) {
            tbl[base] = make_float4(-0.5f * R.x2[e], -0.5f * R.y2[e],
                                    -0.5f * R.z2[e], R.sq[e]);
            smk[base] = R.mk[e];
            base++;
        }
    }
    __syncthreads();
}

// ---------- warp-0-only compaction ----------
template<int E>
static __device__ __forceinline__ void compact_warp(
    float4* tbl, float* smk, int* scnt,
    Regs<E>& R, int gbase, int lane, int j, int newcap)
{
    const float inf = F_INF;
    #pragma unroll
    for (int e = 0; e < E; e++)
        if (gbase + e == j) { R.sq[e] = inf; R.mk[e] = inf; }
    float4 win = tbl[j];
    __syncwarp();
    if (lane == 0) { tbl[newcap - 1] = win; smk[newcap - 1] = inf; }
    int na = 0;
    #pragma unroll
    for (int e = 0; e < E; e++) na += (R.mk[e] != inf);
    int base = atomicAdd(scnt, na);
    #pragma unroll
    for (int e = 0; e < E; e++) {
        if (R.mk[e] != inf) {
            tbl[base] = make_float4(-0.5f * R.x2[e], -0.5f * R.y2[e],
                                    -0.5f * R.z2[e], R.sq[e]);
            smk[base] = R.mk[e];
            base++;
        }
    }
    __syncwarp();
}

template<int E>
static __device__ __forceinline__ void reload(
    const float4* tbl, const float* smk, Regs<E>& R, int gbase, int cap)
{
    #pragma unroll
    for (int e = 0; e < E; e++) {
        int i = gbase + e;
        float4 t = tbl[i];
        R.x2[e] = -2.0f * t.x; R.y2[e] = -2.0f * t.y; R.z2[e] = -2.0f * t.z;
        R.sq[e] = (i == cap - 1) ? F_INF : t.w;     // winner pad inert
        R.mk[e] = smk[i];
    }
}

__global__ __launch_bounds__(NT, 1)
void ph_kernel(const float* __restrict__ x,
               const float* __restrict__ filt,
               float* __restrict__ out,
               int B, int F)
{
    __shared__ __align__(16) float4 tbl[NPTS];     // raw (x,y,z,|x|^2), reused
    __shared__ __align__(16) float  sdeath[NPTS];
    __shared__ float  smk[1536];
    __shared__ u64    wred[2][NW];
    __shared__ int    scnt[4];

    const int b     = blockIdx.x;
    const int tid   = threadIdx.x;
    const int lane  = tid & 31;
    const int wid   = tid >> 5;
    const float inf = F_INF;

    const float* xb = x + (long)b * NPTS * 3;

    // ---- load: premultiplied regs (E=16), raw table ----
    Regs<16> R1;
    {
        int gbase = tid << 4;
        #pragma unroll
        for (int e = 0; e < 16; e++) {
            int i = gbase + e;
            float a = xb[3*i + 0];
            float c = xb[3*i + 1];
            float d = xb[3*i + 2];
            float s = fmaf(a, a, fmaf(c, c, d * d));
            R1.x2[e] = -2.0f * a; R1.y2[e] = -2.0f * c; R1.z2[e] = -2.0f * d;
            R1.sq[e] = s; R1.mk[e] = inf;
            tbl[i] = make_float4(a, c, d, s);
        }
    }
    if (tid < 4) scnt[tid] = 0;
    __syncthreads();

    int j = 0, p = 0;

    // ---- P1: cap 2048, E16, steps 0..511 ----
    prim_run<16>(tbl, sdeath, wred, R1, tid << 4, tid, wid, j, p, 0, 512);

    // ---- compact -> 1536; E12, steps 512..1023 ----
    compact_block<16>(tbl, smk, &scnt[0], R1, tid << 4, tid, j, 1536);
    Regs<12> R2;
    reload<12>(tbl, smk, R2, tid * 12, 1536);
    j = 1535;
    prim_run<12>(tbl, sdeath, wred, R2, tid * 12, tid, wid, j, p, 512, 512);

    // ---- compact -> 1024; E8, steps 1024..1535 ----
    compact_block<12>(tbl, smk, &scnt[1], R2, tid * 12, tid, j, 1024);
    Regs<8> R3;
    reload<8>(tbl, smk, R3, tid << 3, 1024);
    j = 1023;
    prim_run<8>(tbl, sdeath, wred, R3, tid << 3, tid, wid, j, p, 1024, 512);

    // ---- compact -> 512; single warp from here (E16/lane), steps 1536..1791 ----
    compact_block<8>(tbl, smk, &scnt[2], R3, tid << 3, tid, j, 512);
    if (wid == 0) {
        Regs<16> Q1;
        reload<16>(tbl, smk, Q1, lane << 4, 512);
        int jw = 511;
        prim_warp<16>(tbl, sdeath, Q1, lane << 4, lane, jw, 1536, 256);

        // warp-local compact -> 256; E8/lane, steps 1792..2046
        compact_warp<16>(tbl, smk, &scnt[3], Q1, lane << 4, lane, jw, 256);
        Regs<8> Q2;
        reload<8>(tbl, smk, Q2, lane << 3, 256);
        jw = 255;
        prim_warp<8>(tbl, sdeath, Q2, lane << 3, lane, jw, 1792, 255);
    }
    __syncthreads();

    // ---- d^2 -> death = sqrt(d2); pad slot 2047 with +INF ----
    #pragma unroll
    for (int e = 0; e < 16; e++) {
        int i = (tid << 4) + e;
        float d2 = sdeath[i];
        sdeath[i] = (i < NPTS - 1) ? sqrtf(d2) : inf;
    }
    __syncthreads();

    const long dgm_base = (long)b * 3 * MAXPTS * 2;                     // diagrams [B,3,100,2]
    const long bet_base = (long)B * 3 * MAXPTS * 2 + (long)b * 3 * F;   // betti    [B,3,F]

    // ---- zero-fill H1/H2 diagram slices and betti rows 1,2 ----
    for (int i = tid; i < 2 * MAXPTS * 2; i += NT)
        out[dgm_base + MAXPTS * 2 + i] = 0.0f;
    for (int i = tid; i < 2 * F; i += NT)
        out[bet_base + F + i] = 0.0f;

    // ---- Betti-0: one threshold per thread, float4 smem scan ----
    if (tid < F) {
        float ff = filt[tid];
        int cnt = 0;
        for (int i = 0; i < NPTS; i += 4) {
            float4 v = *reinterpret_cast<const float4*>(&sdeath[i]);
            cnt += (v.x <= ff) + (v.y <= ff) + (v.z <= ff) + (v.w <= ff);
        }
        out[bet_base + tid] = (float)(NPTS - cnt);
    }
    __syncthreads();

    // ---- top-100 deaths desc: iterative max extraction ----
    int jp = -1;
    p = 0;
    const int gbase = tid << 4;
    #pragma unroll 1
    for (int k = 0; k < MAXPTS; k++) {
        float bv[16];
        #pragma unroll
        for (int e = 0; e < 16; e++) {
            int gi = gbase + e;
            float v = sdeath[gi];
            bv[e] = (gi == jp || gi == NPTS - 1) ? 0.0f : v;  // mask pending + INF pad
        }
        float tv = vmax_tree<16>(bv);
        u32 vb = __float_as_uint(tv);
        u32 r1 = __reduce_max_sync(0xffffffffu, vb);
        int te = idx_of<16>(bv, tv);
        if (vb == r1)
            wred[p][wid] = ((u64)r1 << 32) | (u64)(u32)(gbase + te);
        if (tid == 0 && jp >= 0) sdeath[jp] = 0.0f;   // persist removal

        __syncthreads();

        u64 a0 = umax64(wred[p][0], wred[p][1]);
        u64 a1 = umax64(wred[p][2], wred[p][3]);
        a0 = umax64(a0, a1);

        if (tid == 0) {
            out[dgm_base + 2 * k + 0] = 0.0f;
            out[dgm_base + 2 * k + 1] = __uint_as_float((u32)(a0 >> 32));
        }
        jp = (int)(u32)a0;
        p ^= 1;
    }
}

extern "C" void kernel_launch(void* const* d_in, const int* in_sizes, int n_in,
                              void* d_out, int out_size)
{
    const float* x    = (const float*)d_in[0];
    const float* filt = (const float*)d_in[1];
    float* out        = (float*)d_out;

    int B = in_sizes[0] / (NPTS * 3);
    int F = in_sizes[1];

    ph_kernel<<<B, NT>>>(x, filt, out, B, F);
}

// round 13
// speedup vs baseline: 1.2582x; 1.2582x over previous
#include <cuda_runtime.h>
#include <math.h>

#define NPTS   2048
#define NT     128
#define NW     (NT/32)      // 4 warps
#define MAXPTS 100
#define F_INF  (__int_as_float(0x7f800000))

typedef unsigned long long u64;
typedef unsigned int       u32;

static __device__ __forceinline__ u64 umin64(u64 a, u64 b) { return a < b ? a : b; }
static __device__ __forceinline__ u64 umax64(u64 a, u64 b) { return a > b ? a : b; }

template<int E> struct Regs { float x2[E], y2[E], z2[E], sq[E], mk[E]; };

// per-thread argmin: fold tail onto largest pow2 <= E, then halve (compare-select)
template<int E>
static __device__ __forceinline__ void argmin_tree(const float (&v)[E],
                                                   float& outv, int& outi)
{
    float bv[E]; int bi[E];
    #pragma unroll
    for (int e = 0; e < E; e++) { bv[e] = v[e]; bi[e] = e; }
    constexpr int T = ((E & (E - 1)) == 0) ? E : (E > 8 ? 8 : (E > 4 ? 4 : 2));
    #pragma unroll
    for (int e = T; e < E; e++) {
        bool c = bv[e] < bv[e - T];
        bv[e - T] = c ? bv[e] : bv[e - T];
        bi[e - T] = c ? bi[e] : bi[e - T];
    }
    #pragma unroll
    for (int st = T / 2; st >= 1; st >>= 1) {
        #pragma unroll
        for (int e = 0; e < st; e++) {
            bool c = bv[e + st] < bv[e];
            bv[e] = c ? bv[e + st] : bv[e];
            bi[e] = c ? bi[e + st] : bi[e];
        }
    }
    outv = bv[0]; outi = bi[0];
}

// ---------- multi-warp Prim phase (tbl = raw (x,y,z,|x|^2); regs hold -2x) ----------
template<int E>
static __device__ __forceinline__ void prim_run(
    const float4* __restrict__ tbl, float* __restrict__ sdeath,
    u64 (&wred)[2][NW], Regs<E>& R,
    int gbase, int tid, int wid,
    int& j, int& p, int step0, int nsteps)
{
    const float inf = F_INF;
    #pragma unroll 1
    for (int s = 0; s < nsteps; s++) {
        float4 q = tbl[j];                        // LDS.128 broadcast
        #pragma unroll
        for (int e = 0; e < E; e++) {
            int gi = gbase + e;
            bool rem = (gi == j);
            float rs = rem ? inf : R.sq[e];       // permanent poison of removed vertex
            R.sq[e] = rs;
            float acc = fmaf(q.x, R.x2[e], rs + q.w);
            acc = fmaf(q.y, R.y2[e], acc);
            acc = fmaf(q.z, R.z2[e], acc);
            float mi = rem ? inf : R.mk[e];
            R.mk[e] = fminf(mi, fabsf(acc));      // >=0 -> u32 bit-order exact
        }
        float tm; int te;
        argmin_tree<E>(R.mk, tm, te);
        u32 ti = (u32)(gbase + te);

        u32 vb = __float_as_uint(tm);
        u32 r1 = __reduce_min_sync(0xffffffffu, vb);
        if (vb == r1) wred[p][wid] = ((u64)r1 << 32) | (u64)ti;

        __syncthreads();

        u64 a0 = umin64(wred[p][0], wred[p][1]);
        u64 a1 = umin64(wred[p][2], wred[p][3]);
        a0 = umin64(a0, a1);
        if (tid == 0) sdeath[step0 + s] = __uint_as_float((u32)(a0 >> 32));
        j = (int)(u32)a0;
        p ^= 1;
    }
}

// ---------- single-warp Prim phase (warp 0, no block barriers) ----------
template<int E>
static __device__ __forceinline__ void prim_warp(
    const float4* __restrict__ tbl, float* __restrict__ sdeath,
    Regs<E>& R, int gbase, int lane, int& j, int step0, int nsteps)
{
    const float inf = F_INF;
    #pragma unroll 1
    for (int s = 0; s < nsteps; s++) {
        float4 q = tbl[j];
        #pragma unroll
        for (int e = 0; e < E; e++) {
            int gi = gbase + e;
            bool rem = (gi == j);
            float rs = rem ? inf : R.sq[e];
            R.sq[e] = rs;
            float acc = fmaf(q.x, R.x2[e], rs + q.w);
            acc = fmaf(q.y, R.y2[e], acc);
            acc = fmaf(q.z, R.z2[e], acc);
            float mi = rem ? inf : R.mk[e];
            R.mk[e] = fminf(mi, fabsf(acc));
        }
        float tm; int te;
        argmin_tree<E>(R.mk, tm, te);
        u32 ti = (u32)(gbase + te);

        u32 vb = __float_as_uint(tm);
        u32 r1 = __reduce_min_sync(0xffffffffu, vb);
        u32 msk = __ballot_sync(0xffffffffu, vb == r1);
        int src = __ffs(msk) - 1;
        j = __shfl_sync(0xffffffffu, (int)ti, src);
        if (lane == 0) sdeath[step0 + s] = __uint_as_float(r1);
    }
}

// ---------- block-wide compaction: alive -> tbl[0..newcap-2], winner at newcap-1 ----------
template<int E>
static __device__ __forceinline__ void compact_block(
    float4* tbl, float* smk, int* scnt,
    Regs<E>& R, int gbase, int tid, int j, int newcap)
{
    const float inf = F_INF;
    #pragma unroll
    for (int e = 0; e < E; e++)
        if (gbase + e == j) { R.sq[e] = inf; R.mk[e] = inf; }   // pending poison
    float4 win = tbl[j];                    // read winner BEFORE overwrite
    __syncthreads();
    if (tid == 0) { tbl[newcap - 1] = win; smk[newcap - 1] = inf; }
    int na = 0;
    #pragma unroll
    for (int e = 0; e < E; e++) na += (R.mk[e] != inf);
    int base = atomicAdd(scnt, na);
    #pragma unroll
    for (int e = 0; e < E; e++) {
        if (R.mk[e] != inf) {
            tbl[base] = make_float4(-0.5f * R.x2[e], -0.5f * R.y2[e],
                                    -0.5f * R.z2[e], R.sq[e]);
            smk[base] = R.mk[e];
            base++;
        }
    }
    __syncthreads();
}

// ---------- warp-0-only compaction ----------
template<int E>
static __device__ __forceinline__ void compact_warp(
    float4* tbl, float* smk, int* scnt,
    Regs<E>& R, int gbase, int lane, int j, int newcap)
{
    const float inf = F_INF;
    #pragma unroll
    for (int e = 0; e < E; e++)
        if (gbase + e == j) { R.sq[e] = inf; R.mk[e] = inf; }
    float4 win = tbl[j];
    __syncwarp();
    if (lane == 0) { tbl[newcap - 1] = win; smk[newcap - 1] = inf; }
    int na = 0;
    #pragma unroll
    for (int e = 0; e < E; e++) na += (R.mk[e] != inf);
    int base = atomicAdd(scnt, na);
    #pragma unroll
    for (int e = 0; e < E; e++) {
        if (R.mk[e] != inf) {
            tbl[base] = make_float4(-0.5f * R.x2[e], -0.5f * R.y2[e],
                                    -0.5f * R.z2[e], R.sq[e]);
            smk[base] = R.mk[e];
            base++;
        }
    }
    __syncwarp();
}

template<int E>
static __device__ __forceinline__ void reload(
    const float4* tbl, const float* smk, Regs<E>& R, int gbase, int cap)
{
    #pragma unroll
    for (int e = 0; e < E; e++) {
        int i = gbase + e;
        float4 t = tbl[i];
        R.x2[e] = -2.0f * t.x; R.y2[e] = -2.0f * t.y; R.z2[e] = -2.0f * t.z;
        R.sq[e] = (i == cap - 1) ? F_INF : t.w;     // winner pad inert
        R.mk[e] = smk[i];
    }
}

__global__ __launch_bounds__(NT, 1)
void ph_kernel(const float* __restrict__ x,
               const float* __restrict__ filt,
               float* __restrict__ out,
               int B, int F)
{
    __shared__ __align__(16) float4 tbl[NPTS];     // raw (x,y,z,|x|^2), reused
    __shared__ __align__(16) float  sdeath[NPTS];
    __shared__ float  smk[1792];
    __shared__ u64    wred[2][NW];
    __shared__ int    scnt[7];

    const int b     = blockIdx.x;
    const int tid   = threadIdx.x;
    const int lane  = tid & 31;
    const int wid   = tid >> 5;
    const float inf = F_INF;

    const float* xb = x + (long)b * NPTS * 3;

    // ---- load: premultiplied regs (E=16), raw table ----
    Regs<16> R1;
    {
        int gbase = tid << 4;
        #pragma unroll
        for (int e = 0; e < 16; e++) {
            int i = gbase + e;
            float a = xb[3*i + 0];
            float c = xb[3*i + 1];
            float d = xb[3*i + 2];
            float s = fmaf(a, a, fmaf(c, c, d * d));
            R1.x2[e] = -2.0f * a; R1.y2[e] = -2.0f * c; R1.z2[e] = -2.0f * d;
            R1.sq[e] = s; R1.mk[e] = inf;
            tbl[i] = make_float4(a, c, d, s);
        }
    }
    if (tid < 7) scnt[tid] = 0;
    __syncthreads();

    int j = 0, p = 0;

    // ---- dense staircase: compact every 256 steps ----
    // cap 2048, E16, steps 0..255
    prim_run<16>(tbl, sdeath, wred, R1, tid << 4, tid, wid, j, p, 0, 256);

    // -> 1792, E14, steps 256..511
    compact_block<16>(tbl, smk, &scnt[0], R1, tid << 4, tid, j, 1792);
    Regs<14> R2;
    reload<14>(tbl, smk, R2, tid * 14, 1792);
    j = 1791;
    prim_run<14>(tbl, sdeath, wred, R2, tid * 14, tid, wid, j, p, 256, 256);

    // -> 1536, E12, steps 512..767
    compact_block<14>(tbl, smk, &scnt[1], R2, tid * 14, tid, j, 1536);
    Regs<12> R3;
    reload<12>(tbl, smk, R3, tid * 12, 1536);
    j = 1535;
    prim_run<12>(tbl, sdeath, wred, R3, tid * 12, tid, wid, j, p, 512, 256);

    // -> 1280, E10, steps 768..1023
    compact_block<12>(tbl, smk, &scnt[2], R3, tid * 12, tid, j, 1280);
    Regs<10> R4;
    reload<10>(tbl, smk, R4, tid * 10, 1280);
    j = 1279;
    prim_run<10>(tbl, sdeath, wred, R4, tid * 10, tid, wid, j, p, 768, 256);

    // -> 1024, E8, steps 1024..1279
    compact_block<10>(tbl, smk, &scnt[3], R4, tid * 10, tid, j, 1024);
    Regs<8> R5;
    reload<8>(tbl, smk, R5, tid << 3, 1024);
    j = 1023;
    prim_run<8>(tbl, sdeath, wred, R5, tid << 3, tid, wid, j, p, 1024, 256);

    // -> 768, E6, steps 1280..1535
    compact_block<8>(tbl, smk, &scnt[4], R5, tid << 3, tid, j, 768);
    Regs<6> R6;
    reload<6>(tbl, smk, R6, tid * 6, 768);
    j = 767;
    prim_run<6>(tbl, sdeath, wred, R6, tid * 6, tid, wid, j, p, 1280, 256);

    // -> 512: single warp, E16/lane, steps 1536..1791
    compact_block<6>(tbl, smk, &scnt[5], R6, tid * 6, tid, j, 512);
    if (wid == 0) {
        Regs<16> Q1;
        reload<16>(tbl, smk, Q1, lane << 4, 512);
        int jw = 511;
        prim_warp<16>(tbl, sdeath, Q1, lane << 4, lane, jw, 1536, 256);

        // warp-local compact -> 256; E8/lane, steps 1792..2046
        compact_warp<16>(tbl, smk, &scnt[6], Q1, lane << 4, lane, jw, 256);
        Regs<8> Q2;
        reload<8>(tbl, smk, Q2, lane << 3, 256);
        jw = 255;
        prim_warp<8>(tbl, sdeath, Q2, lane << 3, lane, jw, 1792, 255);
    }
    __syncthreads();

    // ---- d^2 -> death = sqrt(d2); pad slot 2047 with +INF ----
    #pragma unroll
    for (int e = 0; e < 16; e++) {
        int i = (tid << 4) + e;
        float d2 = sdeath[i];
        sdeath[i] = (i < NPTS - 1) ? sqrtf(d2) : inf;
    }
    __syncthreads();

    const long dgm_base = (long)b * 3 * MAXPTS * 2;                     // diagrams [B,3,100,2]
    const long bet_base = (long)B * 3 * MAXPTS * 2 + (long)b * 3 * F;   // betti    [B,3,F]

    // ---- zero-fill H1/H2 diagram slices and betti rows 1,2 ----
    for (int i = tid; i < 2 * MAXPTS * 2; i += NT)
        out[dgm_base + MAXPTS * 2 + i] = 0.0f;
    for (int i = tid; i < 2 * F; i += NT)
        out[bet_base + F + i] = 0.0f;

    // ---- Betti-0: one threshold per thread, float4 smem scan ----
    if (tid < F) {
        float ff = filt[tid];
        int cnt = 0;
        for (int i = 0; i < NPTS; i += 4) {
            float4 v = *reinterpret_cast<const float4*>(&sdeath[i]);
            cnt += (v.x <= ff) + (v.y <= ff) + (v.z <= ff) + (v.w <= ff);
        }
        out[bet_base + tid] = (float)(NPTS - cnt);
    }
    __syncthreads();

    // ---- top-100 deaths desc: iterative max extraction (R11 form) ----
    int jp = -1;
    p = 0;
    const int gbase = tid << 4;
    #pragma unroll 1
    for (int k = 0; k < MAXPTS; k++) {
        float bv[16]; int bi[16];
        #pragma unroll
        for (int e = 0; e < 16; e++) {
            int gi = gbase + e;
            float v = sdeath[gi];
            bv[e] = (gi == jp || gi == NPTS - 1) ? 0.0f : v;  // mask pending + INF pad
            bi[e] = e;
        }
        #pragma unroll
        for (int st = 8; st >= 1; st >>= 1) {
            #pragma unroll
            for (int e = 0; e < st; e++) {
                bool c = bv[e+st] > bv[e];
                bv[e] = c ? bv[e+st] : bv[e];
                bi[e] = c ? bi[e+st] : bi[e];
            }
        }
        u32 ti = (u32)(gbase + bi[0]);
        u32 vb = __float_as_uint(bv[0]);
        u32 r1 = __reduce_max_sync(0xffffffffu, vb);
        if (vb == r1) wred[p][wid] = ((u64)r1 << 32) | (u64)ti;
        if (tid == 0 && jp >= 0) sdeath[jp] = 0.0f;   // persist removal

        __syncthreads();

        u64 a0 = umax64(wred[p][0], wred[p][1]);
        u64 a1 = umax64(wred[p][2], wred[p][3]);
        a0 = umax64(a0, a1);

        if (tid == 0) {
            out[dgm_base + 2 * k + 0] = 0.0f;
            out[dgm_base + 2 * k + 1] = __uint_as_float((u32)(a0 >> 32));
        }
        jp = (int)(u32)a0;
        p ^= 1;
    }
}

extern "C" void kernel_launch(void* const* d_in, const int* in_sizes, int n_in,
                              void* d_out, int out_size)
{
    const float* x    = (const float*)d_in[0];
    const float* filt = (const float*)d_in[1];
    float* out        = (float*)d_out;

    int B = in_sizes[0] / (NPTS * 3);
    int F = in_sizes[1];

    ph_kernel<<<B, NT>>>(x, filt, out, B, F);
}

// round 14
// speedup vs baseline: 1.3601x; 1.0810x over previous
#include <cuda_runtime.h>
#include <math.h>

#define NPTS   2048
#define NT     128
#define NW     (NT/32)      // 4 warps
#define MAXPTS 100
#define F_INF  (__int_as_float(0x7f800000))

typedef unsigned long long u64;
typedef unsigned int       u32;

static __device__ __forceinline__ u64 umin64(u64 a, u64 b) { return a < b ? a : b; }
static __device__ __forceinline__ u64 umax64(u64 a, u64 b) { return a > b ? a : b; }

template<int E> struct Regs { float x2[E], y2[E], z2[E], sq[E], mk[E]; };

// per-thread argmin: fold tail onto largest pow2 <= E, then halve (compare-select)
template<int E>
static __device__ __forceinline__ void argmin_tree(const float (&v)[E],
                                                   float& outv, int& outi)
{
    float bv[E]; int bi[E];
    #pragma unroll
    for (int e = 0; e < E; e++) { bv[e] = v[e]; bi[e] = e; }
    constexpr int T = ((E & (E - 1)) == 0) ? E : (E > 8 ? 8 : (E > 4 ? 4 : 2));
    #pragma unroll
    for (int e = T; e < E; e++) {
        bool c = bv[e] < bv[e - T];
        bv[e - T] = c ? bv[e] : bv[e - T];
        bi[e - T] = c ? bi[e] : bi[e - T];
    }
    #pragma unroll
    for (int st = T / 2; st >= 1; st >>= 1) {
        #pragma unroll
        for (int e = 0; e < st; e++) {
            bool c = bv[e + st] < bv[e];
            bv[e] = c ? bv[e + st] : bv[e];
            bi[e] = c ? bi[e + st] : bi[e];
        }
    }
    outv = bv[0]; outi = bi[0];
}

// ---------- multi-warp Prim phase (tbl = raw (x,y,z,|x|^2); regs hold -2x) ----------
template<int E>
static __device__ __forceinline__ void prim_run(
    const float4* __restrict__ tbl, float* __restrict__ sdeath,
    u64 (&wred)[2][NW], Regs<E>& R,
    int gbase, int tid, int wid,
    int& j, int& p, int step0, int nsteps)
{
    const float inf = F_INF;
    #pragma unroll 1
    for (int s = 0; s < nsteps; s++) {
        float4 q = tbl[j];                        // LDS.128 broadcast
        #pragma unroll
        for (int e = 0; e < E; e++) {
            int gi = gbase + e;
            bool rem = (gi == j);
            float rs = rem ? inf : R.sq[e];       // permanent poison of removed vertex
            R.sq[e] = rs;
            float acc = fmaf(q.x, R.x2[e], rs + q.w);
            acc = fmaf(q.y, R.y2[e], acc);
            acc = fmaf(q.z, R.z2[e], acc);
            float mi = rem ? inf : R.mk[e];
            R.mk[e] = fminf(mi, fabsf(acc));      // >=0 -> u32 bit-order exact
        }
        float tm; int te;
        argmin_tree<E>(R.mk, tm, te);
        u32 ti = (u32)(gbase + te);

        u32 vb = __float_as_uint(tm);
        u32 r1 = __reduce_min_sync(0xffffffffu, vb);
        if (vb == r1) wred[p][wid] = ((u64)r1 << 32) | (u64)ti;

        __syncthreads();

        u64 a0 = umin64(wred[p][0], wred[p][1]);
        u64 a1 = umin64(wred[p][2], wred[p][3]);
        a0 = umin64(a0, a1);
        if (tid == 0) sdeath[step0 + s] = __uint_as_float((u32)(a0 >> 32));
        j = (int)(u32)a0;
        p ^= 1;
    }
}

// ---------- single-warp Prim phase (warp 0, no block barriers) ----------
template<int E>
static __device__ __forceinline__ void prim_warp(
    const float4* __restrict__ tbl, float* __restrict__ sdeath,
    Regs<E>& R, int gbase, int lane, int& j, int step0, int nsteps)
{
    const float inf = F_INF;
    #pragma unroll 1
    for (int s = 0; s < nsteps; s++) {
        float4 q = tbl[j];
        #pragma unroll
        for (int e = 0; e < E; e++) {
            int gi = gbase + e;
            bool rem = (gi == j);
            float rs = rem ? inf : R.sq[e];
            R.sq[e] = rs;
            float acc = fmaf(q.x, R.x2[e], rs + q.w);
            acc = fmaf(q.y, R.y2[e], acc);
            acc = fmaf(q.z, R.z2[e], acc);
            float mi = rem ? inf : R.mk[e];
            R.mk[e] = fminf(mi, fabsf(acc));
        }
        float tm; int te;
        argmin_tree<E>(R.mk, tm, te);
        u32 ti = (u32)(gbase + te);

        u32 vb = __float_as_uint(tm);
        u32 r1 = __reduce_min_sync(0xffffffffu, vb);
        u32 msk = __ballot_sync(0xffffffffu, vb == r1);
        int src = __ffs(msk) - 1;
        j = __shfl_sync(0xffffffffu, (int)ti, src);
        if (lane == 0) sdeath[step0 + s] = __uint_as_float(r1);
    }
}

// ---------- block-wide compaction: alive -> tbl[0..newcap-2], winner at newcap-1 ----------
template<int E>
static __device__ __forceinline__ void compact_block(
    float4* tbl, float* smk, int* scnt,
    Regs<E>& R, int gbase, int tid, int j, int newcap)
{
    const float inf = F_INF;
    #pragma unroll
    for (int e = 0; e < E; e++)
        if (gbase + e == j) { R.sq[e] = inf; R.mk[e] = inf; }   // pending poison
    float4 win = tbl[j];                    // read winner BEFORE overwrite
    __syncthreads();
    if (tid == 0) { tbl[newcap - 1] = win; smk[newcap - 1] = inf; }
    int na = 0;
    #pragma unroll
    for (int e = 0; e < E; e++) na += (R.mk[e] != inf);
    int base = atomicAdd(scnt, na);
    #pragma unroll
    for (int e = 0; e < E; e++) {
        if (R.mk[e] != inf) {
            tbl[base] = make_float4(-0.5f * R.x2[e], -0.5f * R.y2[e],
                                    -0.5f * R.z2[e], R.sq[e]);
            smk[base] = R.mk[e];
            base++;
        }
    }
    __syncthreads();
}

// ---------- warp-0-only compaction ----------
template<int E>
static __device__ __forceinline__ void compact_warp(
    float4* tbl, float* smk, int* scnt,
    Regs<E>& R, int gbase, int lane, int j, int newcap)
{
    const float inf = F_INF;
    #pragma unroll
    for (int e = 0; e < E; e++)
        if (gbase + e == j) { R.sq[e] = inf; R.mk[e] = inf; }
    float4 win = tbl[j];
    __syncwarp();
    if (lane == 0) { tbl[newcap - 1] = win; smk[newcap - 1] = inf; }
    int na = 0;
    #pragma unroll
    for (int e = 0; e < E; e++) na += (R.mk[e] != inf);
    int base = atomicAdd(scnt, na);
    #pragma unroll
    for (int e = 0; e < E; e++) {
        if (R.mk[e] != inf) {
            tbl[base] = make_float4(-0.5f * R.x2[e], -0.5f * R.y2[e],
                                    -0.5f * R.z2[e], R.sq[e]);
            smk[base] = R.mk[e];
            base++;
        }
    }
    __syncwarp();
}

template<int E>
static __device__ __forceinline__ void reload(
    const float4* tbl, const float* smk, Regs<E>& R, int gbase, int cap)
{
    #pragma unroll
    for (int e = 0; e < E; e++) {
        int i = gbase + e;
        float4 t = tbl[i];
        R.x2[e] = -2.0f * t.x; R.y2[e] = -2.0f * t.y; R.z2[e] = -2.0f * t.z;
        R.sq[e] = (i == cap - 1) ? F_INF : t.w;     // winner pad inert
        R.mk[e] = smk[i];
    }
}

__global__ __launch_bounds__(NT, 1)
void ph_kernel(const float* __restrict__ x,
               const float* __restrict__ filt,
               float* __restrict__ out,
               int B, int F)
{
    __shared__ __align__(16) float4 tbl[NPTS];     // raw (x,y,z,|x|^2), reused
    __shared__ __align__(16) float  sdeath[NPTS];
    __shared__ float  smk[1792];
    __shared__ u64    wred[2][NW];
    __shared__ int    scnt[8];

    const int b     = blockIdx.x;
    const int tid   = threadIdx.x;
    const int lane  = tid & 31;
    const int wid   = tid >> 5;
    const float inf = F_INF;

    const float* xb = x + (long)b * NPTS * 3;

    // ---- load: premultiplied regs (E=16), raw table ----
    Regs<16> R1;
    {
        int gbase = tid << 4;
        #pragma unroll
        for (int e = 0; e < 16; e++) {
            int i = gbase + e;
            float a = xb[3*i + 0];
            float c = xb[3*i + 1];
            float d = xb[3*i + 2];
            float s = fmaf(a, a, fmaf(c, c, d * d));
            R1.x2[e] = -2.0f * a; R1.y2[e] = -2.0f * c; R1.z2[e] = -2.0f * d;
            R1.sq[e] = s; R1.mk[e] = inf;
            tbl[i] = make_float4(a, c, d, s);
        }
    }
    if (tid < 8) scnt[tid] = 0;
    __syncthreads();

    int j = 0, p = 0;

    // ---- dense staircase: compact every 256 steps (multi-warp region) ----
    // cap 2048, E16, steps 0..255
    prim_run<16>(tbl, sdeath, wred, R1, tid << 4, tid, wid, j, p, 0, 256);

    // -> 1792, E14, steps 256..511
    compact_block<16>(tbl, smk, &scnt[0], R1, tid << 4, tid, j, 1792);
    Regs<14> R2;
    reload<14>(tbl, smk, R2, tid * 14, 1792);
    j = 1791;
    prim_run<14>(tbl, sdeath, wred, R2, tid * 14, tid, wid, j, p, 256, 256);

    // -> 1536, E12, steps 512..767
    compact_block<14>(tbl, smk, &scnt[1], R2, tid * 14, tid, j, 1536);
    Regs<12> R3;
    reload<12>(tbl, smk, R3, tid * 12, 1536);
    j = 1535;
    prim_run<12>(tbl, sdeath, wred, R3, tid * 12, tid, wid, j, p, 512, 256);

    // -> 1280, E10, steps 768..1023
    compact_block<12>(tbl, smk, &scnt[2], R3, tid * 12, tid, j, 1280);
    Regs<10> R4;
    reload<10>(tbl, smk, R4, tid * 10, 1280);
    j = 1279;
    prim_run<10>(tbl, sdeath, wred, R4, tid * 10, tid, wid, j, p, 768, 256);

    // -> 1024, E8, steps 1024..1279
    compact_block<10>(tbl, smk, &scnt[3], R4, tid * 10, tid, j, 1024);
    Regs<8> R5;
    reload<8>(tbl, smk, R5, tid << 3, 1024);
    j = 1023;
    prim_run<8>(tbl, sdeath, wred, R5, tid << 3, tid, wid, j, p, 1024, 256);

    // -> 768, E6, steps 1280..1535
    compact_block<8>(tbl, smk, &scnt[4], R5, tid << 3, tid, j, 768);
    Regs<6> R6;
    reload<6>(tbl, smk, R6, tid * 6, 768);
    j = 767;
    prim_run<6>(tbl, sdeath, wred, R6, tid * 6, tid, wid, j, p, 1280, 256);

    // -> 512, E4, steps 1536..1791   (R11's proven tail from here)
    compact_block<6>(tbl, smk, &scnt[5], R6, tid * 6, tid, j, 512);
    Regs<4> R7;
    reload<4>(tbl, smk, R7, tid << 2, 512);
    j = 511;
    prim_run<4>(tbl, sdeath, wred, R7, tid << 2, tid, wid, j, p, 1536, 256);

    // -> 256: single warp, E8/lane, steps 1792..2046
    compact_block<4>(tbl, smk, &scnt[6], R7, tid << 2, tid, j, 256);
    if (wid == 0) {
        Regs<8> Q;
        reload<8>(tbl, smk, Q, lane << 3, 256);
        int jw = 255;
        prim_warp<8>(tbl, sdeath, Q, lane << 3, lane, jw, 1792, 255);
    }
    __syncthreads();

    // ---- d^2 -> death = sqrt(d2); pad slot 2047 with +INF ----
    #pragma unroll
    for (int e = 0; e < 16; e++) {
        int i = (tid << 4) + e;
        float d2 = sdeath[i];
        sdeath[i] = (i < NPTS - 1) ? sqrtf(d2) : inf;
    }
    __syncthreads();

    const long dgm_base = (long)b * 3 * MAXPTS * 2;                     // diagrams [B,3,100,2]
    const long bet_base = (long)B * 3 * MAXPTS * 2 + (long)b * 3 * F;   // betti    [B,3,F]

    // ---- zero-fill H1/H2 diagram slices and betti rows 1,2 ----
    for (int i = tid; i < 2 * MAXPTS * 2; i += NT)
        out[dgm_base + MAXPTS * 2 + i] = 0.0f;
    for (int i = tid; i < 2 * F; i += NT)
        out[bet_base + F + i] = 0.0f;

    // ---- Betti-0: one threshold per thread, float4 smem scan ----
    if (tid < F) {
        float ff = filt[tid];
        int cnt = 0;
        for (int i = 0; i < NPTS; i += 4) {
            float4 v = *reinterpret_cast<const float4*>(&sdeath[i]);
            cnt += (v.x <= ff) + (v.y <= ff) + (v.z <= ff) + (v.w <= ff);
        }
        out[bet_base + tid] = (float)(NPTS - cnt);
    }
    __syncthreads();

    // ---- top-100 deaths desc: iterative max extraction (R11 form) ----
    int jp = -1;
    p = 0;
    const int gbase = tid << 4;
    #pragma unroll 1
    for (int k = 0; k < MAXPTS; k++) {
        float bv[16]; int bi[16];
        #pragma unroll
        for (int e = 0; e < 16; e++) {
            int gi = gbase + e;
            float v = sdeath[gi];
            bv[e] = (gi == jp || gi == NPTS - 1) ? 0.0f : v;  // mask pending + INF pad
            bi[e] = e;
        }
        #pragma unroll
        for (int st = 8; st >= 1; st >>= 1) {
            #pragma unroll
            for (int e = 0; e < st; e++) {
                bool c = bv[e+st] > bv[e];
                bv[e] = c ? bv[e+st] : bv[e];
                bi[e] = c ? bi[e+st] : bi[e];
            }
        }
        u32 ti = (u32)(gbase + bi[0]);
        u32 vb = __float_as_uint(bv[0]);
        u32 r1 = __reduce_max_sync(0xffffffffu, vb);
        if (vb == r1) wred[p][wid] = ((u64)r1 << 32) | (u64)ti;
        if (tid == 0 && jp >= 0) sdeath[jp] = 0.0f;   // persist removal

        __syncthreads();

        u64 a0 = umax64(wred[p][0], wred[p][1]);
        u64 a1 = umax64(wred[p][2], wred[p][3]);
        a0 = umax64(a0, a1);

        if (tid == 0) {
            out[dgm_base + 2 * k + 0] = 0.0f;
            out[dgm_base + 2 * k + 1] = __uint_as_float((u32)(a0 >> 32));
        }
        jp = (int)(u32)a0;
        p ^= 1;
    }
}

extern "C" void kernel_launch(void* const* d_in, const int* in_sizes, int n_in,
                              void* d_out, int out_size)
{
    const float* x    = (const float*)d_in[0];
    const float* filt = (const float*)d_in[1];
    float* out        = (float*)d_out;

    int B = in_sizes[0] / (NPTS * 3);
    int F = in_sizes[1];

    ph_kernel<<<B, NT>>>(x, filt, out, B, F);
}